// round 15
// baseline (speedup 1.0000x reference)
#include <cuda_runtime.h>
#include <cuda_bf16.h>
#include <cuda_fp16.h>
#include <math.h>

#define SEQ 512
#define BB  64
#define EMB 512
#define HID 1024
#define NG  4096
#define NM  32768

typedef unsigned long long ull;

// ---------------- device scratch ----------------
__device__ float d_gx[(size_t)SEQ * NG * BB];                  // [s][R][b]
__device__ __align__(16) __half d_wxf[(size_t)2 * NG * EMB];   // Wx fp16 hi/lo, R-order
__device__ float d_bxr[NG];
__device__ __align__(16) __half d_whf[(size_t)2 * NG * HID];   // Wh fp16 hi/lo, cta-slab order
__device__ __align__(16) __half d_ef16[(size_t)NM * EMB];      // gathered emb fp16 [m][k]
__device__ __align__(16) __half d_hf16[3][BB * HID];           // h fp16, triple buffer
__device__ float d_hfin[BB * HID];
__device__ float d_cst[BB * HID];
__device__ int   d_bar4[4];                                    // group barriers

// ---------------- helpers ----------------
__device__ __forceinline__ float sigf(float x) { return 1.0f / (1.0f + __expf(-x)); }

__device__ __forceinline__ void cp16(void* smem_dst, const void* gsrc) {
    unsigned d = (unsigned)__cvta_generic_to_shared(smem_dst);
    asm volatile("cp.async.cg.shared.global [%0], [%1], 16;" :: "r"(d), "l"(gsrc));
}
__device__ __forceinline__ void cp_commit() { asm volatile("cp.async.commit_group;"); }
template <int N> __device__ __forceinline__ void cp_wait() {
    asm volatile("cp.async.wait_group %0;" :: "n"(N));
}
__device__ __forceinline__ unsigned smem_u32(const void* p) {
    return (unsigned)__cvta_generic_to_shared(p);
}
__device__ __forceinline__ void ldm_x4(unsigned& r0, unsigned& r1, unsigned& r2, unsigned& r3,
                                       unsigned addr) {
    asm volatile("ldmatrix.sync.aligned.m8n8.x4.shared.b16 {%0,%1,%2,%3}, [%4];"
                 : "=r"(r0), "=r"(r1), "=r"(r2), "=r"(r3) : "r"(addr));
}
__device__ __forceinline__ void mma16816f16(float* d, const unsigned* a, unsigned b0, unsigned b1) {
    asm volatile(
        "mma.sync.aligned.m16n8k16.row.col.f32.f16.f16.f32 "
        "{%0,%1,%2,%3}, {%4,%5,%6,%7}, {%8,%9}, {%0,%1,%2,%3};"
        : "+f"(d[0]), "+f"(d[1]), "+f"(d[2]), "+f"(d[3])
        : "r"(a[0]), "r"(a[1]), "r"(a[2]), "r"(a[3]), "r"(b0), "r"(b1));
}
// warp-collective wait on group counter
__device__ __forceinline__ void wait_cnt(int g, int target) {
    if ((threadIdx.x & 31) == 0) {
        while (*(volatile int*)&d_bar4[g] < target) { }
    }
    __syncwarp();
}

// =====================================================================
// prepack: Wx fp16 hi/lo R-order; Wh fp16 hi/lo cta-slab order; zero h.
// =====================================================================
__global__ void prepack_kernel(
    const float* __restrict__ W_ii, const float* __restrict__ b_ii, const float* __restrict__ W_hi,
    const float* __restrict__ W_if, const float* __restrict__ b_if, const float* __restrict__ W_hf,
    const float* __restrict__ W_ig, const float* __restrict__ b_ig, const float* __restrict__ W_hg,
    const float* __restrict__ W_io, const float* __restrict__ b_io, const float* __restrict__ W_ho)
{
    const size_t stride = (size_t)gridDim.x * blockDim.x;
    const size_t tid = (size_t)blockIdx.x * blockDim.x + threadIdx.x;

    if (tid < 4) d_bar4[tid] = 0;

    for (size_t i = tid; i < (size_t)NG * EMB; i += stride) {
        int R = (int)(i >> 9), k = (int)(i & 511);
        int cta = R >> 5, g = (R >> 3) & 3, jj = R & 7;
        int j = cta * 8 + jj;
        const float* w = (g == 0) ? W_ii : (g == 1) ? W_if : (g == 2) ? W_ig : W_io;
        float v = w[j * EMB + k];
        __half hi = __float2half_rn(v);
        d_wxf[i] = hi;
        d_wxf[(size_t)NG * EMB + i] = __float2half_rn(v - __half2float(hi));
    }
    for (size_t i = tid; i < NG; i += stride) {
        int R = (int)i;
        int cta = R >> 5, g = (R >> 3) & 3, jj = R & 7;
        int j = cta * 8 + jj;
        const float* b = (g == 0) ? b_ii : (g == 1) ? b_if : (g == 2) ? b_ig : b_io;
        d_bxr[R] = b[j];
    }
    for (size_t i = tid; i < (size_t)2 * NG * HID; i += stride) {
        int Re = (int)(i >> 10), k = (int)(i & 1023);
        int cta = Re >> 6, rem = Re & 63;
        int split = rem >> 5, local = rem & 31;
        int g = local >> 3, jj = local & 7;
        int j = cta * 8 + jj;
        const float* w = (g == 0) ? W_hi : (g == 1) ? W_hf : (g == 2) ? W_hg : W_ho;
        float v = w[j * HID + k];
        __half hi = __float2half_rn(v);
        if (split == 0) d_whf[i] = hi;
        else            d_whf[i] = __float2half_rn(v - __half2float(hi));
    }
    for (size_t i = tid; i < BB * HID; i += stride) {
        d_hf16[0][i] = __float2half_rn(0.0f);
        d_hf16[1][i] = __float2half_rn(0.0f);
        d_hf16[2][i] = __float2half_rn(0.0f);
    }
}

// =====================================================================
// gather: e rows m = s*64+b -> single fp16 [m][k].
// =====================================================================
__global__ void gather_kernel(const int* __restrict__ x, const float* __restrict__ emb)
{
    ull* eh = (ull*)d_ef16;
    const size_t stride = (size_t)gridDim.x * blockDim.x;
    for (size_t idx = (size_t)blockIdx.x * blockDim.x + threadIdx.x;
         idx < (size_t)NM * 128; idx += stride) {
        int m = (int)(idx >> 7), q = (int)(idx & 127);
        int s = m >> 6, b = m & 63;
        int tok = __ldg(&x[b * SEQ + s]);
        float4 v = *(const float4*)(emb + (size_t)tok * EMB + q * 4);
        __half h0 = __float2half_rn(v.x), h1 = __float2half_rn(v.y);
        __half h2 = __float2half_rn(v.z), h3 = __float2half_rn(v.w);
        ull pk = (ull)*(unsigned short*)&h0 | ((ull)*(unsigned short*)&h1 << 16)
               | ((ull)*(unsigned short*)&h2 << 32) | ((ull)*(unsigned short*)&h3 << 48);
        eh[(size_t)m * 128 + q] = pk;
    }
}

// =====================================================================
// gx2: fp16 HMMA GEMM  d_gx[s][R][b] = Wx(2-term) x e(fp16) + bias.
// 2 CTAs/SM. (unchanged from 4748us round)
// =====================================================================
#define G2_PITCH 144
#define G2_SPL   18432
#define G2_ABUF  36864
#define G2_OFF_B 73728
#define G2_BBUF  18432
#define G2_SMEM  110592

__global__ void __launch_bounds__(256, 2) gx2_kernel()
{
    extern __shared__ char smc[];
    const unsigned smb = smem_u32(smc);
    const int t = threadIdx.x, w = t >> 5, lane = t & 31;
    const int mty = blockIdx.x;
    const int ntx = blockIdx.y;
    const int wm = w >> 1, wn = w & 1;
    const int lrow = lane & 15;
    const int kh2 = (lane >> 4) * 16;

    float d[2][4][2][4];
#pragma unroll
    for (int mt = 0; mt < 2; mt++)
#pragma unroll
        for (int bt = 0; bt < 4; bt++)
#pragma unroll
            for (int hf = 0; hf < 2; hf++)
#pragma unroll
                for (int q = 0; q < 4; q++) d[mt][bt][hf][q] = 0.0f;

    auto stage = [&](int cb) {
        const int buf = cb & 1;
        char* abase = smc + buf * G2_ABUF;
        char* bbase = smc + G2_OFF_B + buf * G2_BBUF;
#pragma unroll
        for (int i = 0; i < 8; i++) {
            int u = t + i * 256;
            int split = u >> 10, r = (u >> 3) & 127, q = u & 7;
            cp16(abase + split * G2_SPL + r * G2_PITCH + q * 16,
                 d_wxf + (size_t)split * NG * EMB + (size_t)(mty * 128 + r) * EMB + cb * 64 + q * 8);
        }
#pragma unroll
        for (int i = 0; i < 4; i++) {
            int u = t + i * 256;
            int r = u >> 3, q = u & 7;
            cp16(bbase + r * G2_PITCH + q * 16,
                 d_ef16 + (size_t)(ntx * 128 + r) * EMB + cb * 64 + q * 8);
        }
        cp_commit();
    };

    stage(0);

    for (int cb = 0; cb < 8; cb++) {
        if (cb < 7) { stage(cb + 1); cp_wait<1>(); }
        else        { cp_wait<0>(); }
        __syncthreads();

        const unsigned abase = smb + (cb & 1) * G2_ABUF;
        const unsigned bbase = smb + G2_OFF_B + (cb & 1) * G2_BBUF;
#pragma unroll
        for (int k16 = 0; k16 < 4; k16++) {
            const int kB = k16 * 32 + kh2;
            unsigned Ah[2][4], Al[2][4];
#pragma unroll
            for (int mt = 0; mt < 2; mt++) {
                unsigned ar = abase + (wm * 32 + mt * 16 + lrow) * G2_PITCH + kB;
                ldm_x4(Ah[mt][0], Ah[mt][1], Ah[mt][2], Ah[mt][3], ar);
                ldm_x4(Al[mt][0], Al[mt][1], Al[mt][2], Al[mt][3], ar + G2_SPL);
            }
#pragma unroll
            for (int bt = 0; bt < 4; bt++) {
                unsigned br = bbase + (wn * 64 + bt * 16 + lrow) * G2_PITCH + kB;
                unsigned b0, b1, b2, b3;
                ldm_x4(b0, b1, b2, b3, br);
#pragma unroll
                for (int mt = 0; mt < 2; mt++) {
                    mma16816f16(d[mt][bt][0], Ah[mt], b0, b2);
                    mma16816f16(d[mt][bt][1], Ah[mt], b1, b3);
                    mma16816f16(d[mt][bt][0], Al[mt], b0, b2);
                    mma16816f16(d[mt][bt][1], Al[mt], b1, b3);
                }
            }
        }
        __syncthreads();
    }

#pragma unroll
    for (int mt = 0; mt < 2; mt++) {
        int Rg0 = mty * 128 + wm * 32 + mt * 16 + (lane >> 2);
        int Rg1 = Rg0 + 8;
        float bi0 = __ldg(&d_bxr[Rg0]);
        float bi1 = __ldg(&d_bxr[Rg1]);
#pragma unroll
        for (int bt = 0; bt < 4; bt++)
#pragma unroll
            for (int hf = 0; hf < 2; hf++) {
                int col = wn * 64 + bt * 16 + hf * 8 + 2 * (lane & 3);
                int m = ntx * 128 + col;
                int s = m >> 6, b = m & 63;
                float* q = d[mt][bt][hf];
                *(float2*)(&d_gx[((size_t)s * NG + Rg0) * BB + b]) =
                    make_float2(q[0] + bi0, q[1] + bi0);
                *(float2*)(&d_gx[((size_t)s * NG + Rg1) * BB + b]) =
                    make_float2(q[2] + bi1, q[3] + bi1);
            }
    }
}

// =====================================================================
// persistent mma.sync step kernel — pipelined partial barriers.
// 4 group counters (h chunk kb produced by CTAs [32kb,32kb+32)); consumer
// polls group kb (target 32*s) just before staging chunk kb. Triple-
// buffered h in global (skew < 2 steps). No full grid barrier.
// =====================================================================
#define W_PITCH 2064
#define H_PITCH 528
#define HBUF (64 * H_PITCH)
#define OFF_W   0
#define OFF_H   132096
#define OFF_SG  199680
#define OFF_SGX 208384
#define TC_SMEM 217088

__global__ void __launch_bounds__(256, 1) persist_mma_kernel()
{
    extern __shared__ char smc[];
    float* sg  = (float*)(smc + OFF_SG);
    float* sgx = (float*)(smc + OFF_SGX);

    const int t = threadIdx.x, w = t >> 5, lane = t & 31;
    const int cta = blockIdx.x;
    const int wm = w >> 2, wn = w & 3;
    const unsigned smb = smem_u32(smc);

    const char* wsrc = (const char*)(d_whf + (size_t)cta * 64 * HID);
#pragma unroll
    for (int i = 0; i < 32; i++) {
        int u = t + i * 256;
        int r = u >> 7, q = u & 127;
        cp16(smc + OFF_W + r * W_PITCH + q * 16, wsrc + r * 2048 + q * 16);
    }
    cp_commit();

    const int lrow = lane & 15;
    const int kh2 = (lane >> 4) * 16;

    const int be = t & 63, jp = t >> 6;
    float creg[2] = {0.0f, 0.0f};

    // prefetch gx for s = 0
#pragma unroll
    for (int i = 0; i < 2; i++) {
        int u = t + i * 256;
        int r = u >> 4, bq = (u & 15) * 4;
        cp16((char*)sgx + (r * 68 + bq) * 4,
             d_gx + ((size_t)0 * NG + cta * 32 + r) * BB + bq);
    }
    cp_commit();
    cp_wait<0>();
    __syncthreads();

    int hbuf_r = 0;   // s % 3

    for (int s = 0; s < SEQ; s++) {
        const char* hsrc = (const char*)d_hf16[hbuf_r];
        int hbuf_w = hbuf_r + 1; if (hbuf_w == 3) hbuf_w = 0;
        __half* hdst = d_hf16[hbuf_w];
        const int tgt = 32 * s;

        auto stage_h = [&](int kb) {
            char* dst = smc + OFF_H + (kb & 1) * HBUF;
#pragma unroll
            for (int i = 0; i < 8; i++) {
                int u = t + i * 256;
                int r = u >> 5, q = u & 31;
                cp16(dst + r * H_PITCH + q * 16, hsrc + r * 2048 + kb * 512 + q * 16);
            }
            cp_commit();
        };

        wait_cnt(0, tgt);
        stage_h(0);

        float d[2][4];
#pragma unroll
        for (int nt = 0; nt < 2; nt++)
#pragma unroll
            for (int q = 0; q < 4; q++) d[nt][q] = 0.0f;

        for (int kb = 0; kb < 4; kb++) {
            cp_wait<0>();          // chunk kb complete
            __syncthreads();       // all warps done with buf (kb+1)&1
            if (kb < 3) {
                wait_cnt(kb + 1, tgt);
                stage_h(kb + 1);
            }

            const unsigned aw  = smb + OFF_W + (wm * 16 + lrow) * W_PITCH + kb * 512;
            const unsigned awl = aw + 32 * W_PITCH;
            const unsigned hb  = smb + OFF_H + (kb & 1) * HBUF + (wn * 16 + lrow) * H_PITCH;
#pragma unroll
            for (int k16 = 0; k16 < 16; k16++) {
                const int kB = k16 * 32 + kh2;
                unsigned ah[4], al[4];
                unsigned b0, b1, b2, b3;
                ldm_x4(ah[0], ah[1], ah[2], ah[3], aw + kB);
                ldm_x4(al[0], al[1], al[2], al[3], awl + kB);
                ldm_x4(b0, b1, b2, b3, hb + kB);
                mma16816f16(d[0], ah, b0, b2);
                mma16816f16(d[1], ah, b1, b3);
                mma16816f16(d[0], al, b0, b2);
                mma16816f16(d[1], al, b1, b3);
            }
        }
        __syncthreads();           // all compute done before sg overwrite

#pragma unroll
        for (int nt = 0; nt < 2; nt++) {
            int col = wn * 16 + nt * 8 + (lane & 3) * 2;
            int row = wm * 16 + (lane >> 2);
            sg[row * 68 + col]           = d[nt][0];
            sg[row * 68 + col + 1]       = d[nt][1];
            sg[(row + 8) * 68 + col]     = d[nt][2];
            sg[(row + 8) * 68 + col + 1] = d[nt][3];
        }
        __syncthreads();

        unsigned short hph[2];
        float hf[2];
#pragma unroll
        for (int i = 0; i < 2; i++) {
            int jj = 2 * jp + i;
            float g[4];
#pragma unroll
            for (int gg = 0; gg < 4; gg++) {
                int r = gg * 8 + jj;
                g[gg] = sg[r * 68 + be] + sgx[r * 68 + be];
            }
            float it_ = sigf(g[0]);
            float ft  = sigf(g[1]);
            float gt  = tanhf(g[2]);
            float ot  = sigf(g[3]);
            float c = ft * creg[i] + it_ * gt;
            creg[i] = c;
            float h = ot * tanhf(c);
            hf[i] = h;
            __half hh = __float2half_rn(h);
            hph[i] = *(unsigned short*)&hh;
        }
        const int jglob = cta * 8 + 2 * jp;
        *(unsigned*)(&hdst[be * HID + jglob]) = *(unsigned*)hph;
        if (s == SEQ - 1)
            *(float2*)(&d_hfin[be * HID + jglob]) = make_float2(hf[0], hf[1]);

        // ---- signal: h of step s written ----
        __threadfence();
        __syncthreads();
        if (t == 0) atomicAdd(&d_bar4[cta >> 5], 1);

        // ---- prefetch gx(s+1) ----
        if (s + 1 < SEQ) {
#pragma unroll
            for (int i = 0; i < 2; i++) {
                int u = t + i * 256;
                int r = u >> 4, bq = (u & 15) * 4;
                cp16((char*)sgx + (r * 68 + bq) * 4,
                     d_gx + ((size_t)(s + 1) * NG + cta * 32 + r) * BB + bq);
            }
            cp_commit();
        }

        hbuf_r = hbuf_w;
    }

    const int jglob = cta * 8 + 2 * jp;
    *(float2*)(&d_cst[be * HID + jglob]) = make_float2(creg[0], creg[1]);
}

// =====================================================================
// head
// =====================================================================
__global__ void head_kernel(const float* __restrict__ Vw, const float* __restrict__ Vb,
                            float* __restrict__ out)
{
    const int b = blockIdx.x, t = threadIdx.x;
    float s0 = 0.0f, s1 = 0.0f;
    for (int k = t; k < HID; k += 256) {
        float hv = d_hfin[b * HID + k];
        s0 += hv * Vw[k];
        s1 += hv * Vw[HID + k];
        out[128 + b * HID + k] = hv;
        out[128 + BB * HID + b * HID + k] = d_cst[b * HID + k];
    }
    __shared__ float r0[256], r1[256];
    r0[t] = s0; r1[t] = s1;
    __syncthreads();
    for (int off = 128; off > 0; off >>= 1) {
        if (t < off) { r0[t] += r0[t + off]; r1[t] += r1[t + off]; }
        __syncthreads();
    }
    if (t == 0) {
        out[b * 2 + 0] = r0[0] + Vb[0];
        out[b * 2 + 1] = r1[0] + Vb[1];
    }
}

// =====================================================================
extern "C" void kernel_launch(void* const* d_in, const int* in_sizes, int n_in,
                              void* d_out, int out_size)
{
    (void)in_sizes; (void)n_in; (void)out_size;
    const int*   x   = (const int*)d_in[0];
    const float* emb = (const float*)d_in[1];

    cudaFuncSetAttribute(gx2_kernel,         cudaFuncAttributeMaxDynamicSharedMemorySize, G2_SMEM);
    cudaFuncSetAttribute(persist_mma_kernel, cudaFuncAttributeMaxDynamicSharedMemorySize, TC_SMEM);

    prepack_kernel<<<1024, 256>>>(
        (const float*)d_in[2],  (const float*)d_in[3],  (const float*)d_in[4],
        (const float*)d_in[5],  (const float*)d_in[6],  (const float*)d_in[7],
        (const float*)d_in[8],  (const float*)d_in[9],  (const float*)d_in[10],
        (const float*)d_in[11], (const float*)d_in[12], (const float*)d_in[13]);

    gather_kernel<<<2048, 256>>>(x, emb);

    gx2_kernel<<<dim3(32, 256), 256, G2_SMEM>>>();

    persist_mma_kernel<<<128, 256, TC_SMEM>>>();

    head_kernel<<<BB, 256>>>((const float*)d_in[14], (const float*)d_in[15], (float*)d_out);
}

// round 16
// speedup vs baseline: 1.4022x; 1.4022x over previous
#include <cuda_runtime.h>
#include <cuda_bf16.h>
#include <cuda_fp16.h>
#include <math.h>

#define SEQ 512
#define BB  64
#define EMB 512
#define HID 1024
#define NG  4096
#define NM  32768

typedef unsigned long long ull;

// ---------------- device scratch ----------------
__device__ float d_gx[(size_t)SEQ * NG * BB];                  // [s][R][b]
__device__ __align__(16) __half d_wxf[(size_t)NG * EMB];       // Wx fp16 (hi only), R-order
__device__ float d_bxr[NG];
__device__ __align__(16) __half d_whf[(size_t)NG * HID];       // Wh fp16 (hi only), cta-slab order
__device__ __align__(16) __half d_ef16[(size_t)NM * EMB];      // gathered emb fp16 [m][k]
__device__ __align__(16) __half d_hf16[2][BB * HID];           // h fp16, ping-pong
__device__ float d_hfin[BB * HID];
__device__ float d_cst[BB * HID];
__device__ int   d_bar;

// ---------------- helpers ----------------
__device__ __forceinline__ float sigf(float x) { return 1.0f / (1.0f + __expf(-x)); }

__device__ __forceinline__ void cp16(void* smem_dst, const void* gsrc) {
    unsigned d = (unsigned)__cvta_generic_to_shared(smem_dst);
    asm volatile("cp.async.cg.shared.global [%0], [%1], 16;" :: "r"(d), "l"(gsrc));
}
__device__ __forceinline__ void cp_commit() { asm volatile("cp.async.commit_group;"); }
template <int N> __device__ __forceinline__ void cp_wait() {
    asm volatile("cp.async.wait_group %0;" :: "n"(N));
}
__device__ __forceinline__ unsigned smem_u32(const void* p) {
    return (unsigned)__cvta_generic_to_shared(p);
}
__device__ __forceinline__ void ldm_x4(unsigned& r0, unsigned& r1, unsigned& r2, unsigned& r3,
                                       unsigned addr) {
    asm volatile("ldmatrix.sync.aligned.m8n8.x4.shared.b16 {%0,%1,%2,%3}, [%4];"
                 : "=r"(r0), "=r"(r1), "=r"(r2), "=r"(r3) : "r"(addr));
}
__device__ __forceinline__ void mma16816f16(float* d, const unsigned* a, unsigned b0, unsigned b1) {
    asm volatile(
        "mma.sync.aligned.m16n8k16.row.col.f32.f16.f16.f32 "
        "{%0,%1,%2,%3}, {%4,%5,%6,%7}, {%8,%9}, {%0,%1,%2,%3};"
        : "+f"(d[0]), "+f"(d[1]), "+f"(d[2]), "+f"(d[3])
        : "r"(a[0]), "r"(a[1]), "r"(a[2]), "r"(a[3]), "r"(b0), "r"(b1));
}

// =====================================================================
// prepack: Wx fp16 hi R-order; Wh fp16 hi cta-slab order; zero h.
// =====================================================================
__global__ void prepack_kernel(
    const float* __restrict__ W_ii, const float* __restrict__ b_ii, const float* __restrict__ W_hi,
    const float* __restrict__ W_if, const float* __restrict__ b_if, const float* __restrict__ W_hf,
    const float* __restrict__ W_ig, const float* __restrict__ b_ig, const float* __restrict__ W_hg,
    const float* __restrict__ W_io, const float* __restrict__ b_io, const float* __restrict__ W_ho)
{
    const size_t stride = (size_t)gridDim.x * blockDim.x;
    const size_t tid = (size_t)blockIdx.x * blockDim.x + threadIdx.x;

    if (tid == 0) d_bar = 0;

    for (size_t i = tid; i < (size_t)NG * EMB; i += stride) {
        int R = (int)(i >> 9), k = (int)(i & 511);
        int cta = R >> 5, g = (R >> 3) & 3, jj = R & 7;
        int j = cta * 8 + jj;
        const float* w = (g == 0) ? W_ii : (g == 1) ? W_if : (g == 2) ? W_ig : W_io;
        d_wxf[i] = __float2half_rn(w[j * EMB + k]);
    }
    for (size_t i = tid; i < NG; i += stride) {
        int R = (int)i;
        int cta = R >> 5, g = (R >> 3) & 3, jj = R & 7;
        int j = cta * 8 + jj;
        const float* b = (g == 0) ? b_ii : (g == 1) ? b_if : (g == 2) ? b_ig : b_io;
        d_bxr[R] = b[j];
    }
    for (size_t i = tid; i < (size_t)NG * HID; i += stride) {
        int Re = (int)(i >> 10), k = (int)(i & 1023);
        int cta = Re >> 5, local = Re & 31;
        int g = local >> 3, jj = local & 7;
        int j = cta * 8 + jj;
        const float* w = (g == 0) ? W_hi : (g == 1) ? W_hf : (g == 2) ? W_hg : W_ho;
        d_whf[i] = __float2half_rn(w[j * HID + k]);
    }
    for (size_t i = tid; i < BB * HID; i += stride) {
        d_hf16[0][i] = __float2half_rn(0.0f);
        d_hf16[1][i] = __float2half_rn(0.0f);
    }
}

// =====================================================================
// gather: e rows m = s*64+b -> single fp16 [m][k].
// =====================================================================
__global__ void gather_kernel(const int* __restrict__ x, const float* __restrict__ emb)
{
    ull* eh = (ull*)d_ef16;
    const size_t stride = (size_t)gridDim.x * blockDim.x;
    for (size_t idx = (size_t)blockIdx.x * blockDim.x + threadIdx.x;
         idx < (size_t)NM * 128; idx += stride) {
        int m = (int)(idx >> 7), q = (int)(idx & 127);
        int s = m >> 6, b = m & 63;
        int tok = __ldg(&x[b * SEQ + s]);
        float4 v = *(const float4*)(emb + (size_t)tok * EMB + q * 4);
        __half h0 = __float2half_rn(v.x), h1 = __float2half_rn(v.y);
        __half h2 = __float2half_rn(v.z), h3 = __float2half_rn(v.w);
        ull pk = (ull)*(unsigned short*)&h0 | ((ull)*(unsigned short*)&h1 << 16)
               | ((ull)*(unsigned short*)&h2 << 32) | ((ull)*(unsigned short*)&h3 << 48);
        eh[(size_t)m * 128 + q] = pk;
    }
}

// =====================================================================
// gx2: fp16 HMMA GEMM  d_gx[s][R][b] = Wx(hi) x e(fp16) + bias.
// 2 CTAs/SM. Per k16: 2 A ldm (mt), 4 B ldm (bt), 8 mma.
// =====================================================================
#define G2_PITCH 144
#define G2_ABUF  18432            // 128 rows * 144
#define G2_OFF_B 36864            // after 2 A buffers
#define G2_BBUF  18432
#define G2_SMEM  73728

__global__ void __launch_bounds__(256, 2) gx2_kernel()
{
    extern __shared__ char smc[];
    const unsigned smb = smem_u32(smc);
    const int t = threadIdx.x, w = t >> 5, lane = t & 31;
    const int mty = blockIdx.x;
    const int ntx = blockIdx.y;
    const int wm = w >> 1, wn = w & 1;
    const int lrow = lane & 15;
    const int kh2 = (lane >> 4) * 16;

    float d[2][4][2][4];
#pragma unroll
    for (int mt = 0; mt < 2; mt++)
#pragma unroll
        for (int bt = 0; bt < 4; bt++)
#pragma unroll
            for (int hf = 0; hf < 2; hf++)
#pragma unroll
                for (int q = 0; q < 4; q++) d[mt][bt][hf][q] = 0.0f;

    auto stage = [&](int cb) {
        const int buf = cb & 1;
        char* abase = smc + buf * G2_ABUF;
        char* bbase = smc + G2_OFF_B + buf * G2_BBUF;
        // A: 128 rows x 64 k fp16 (1024 cp16)
#pragma unroll
        for (int i = 0; i < 4; i++) {
            int u = t + i * 256;
            int r = u >> 3, q = u & 7;
            cp16(abase + r * G2_PITCH + q * 16,
                 d_wxf + (size_t)(mty * 128 + r) * EMB + cb * 64 + q * 8);
        }
        // B: 128 rows x 64 k fp16 (1024 cp16)
#pragma unroll
        for (int i = 0; i < 4; i++) {
            int u = t + i * 256;
            int r = u >> 3, q = u & 7;
            cp16(bbase + r * G2_PITCH + q * 16,
                 d_ef16 + (size_t)(ntx * 128 + r) * EMB + cb * 64 + q * 8);
        }
        cp_commit();
    };

    stage(0);

    for (int cb = 0; cb < 8; cb++) {
        if (cb < 7) { stage(cb + 1); cp_wait<1>(); }
        else        { cp_wait<0>(); }
        __syncthreads();

        const unsigned abase = smb + (cb & 1) * G2_ABUF;
        const unsigned bbase = smb + G2_OFF_B + (cb & 1) * G2_BBUF;
#pragma unroll
        for (int k16 = 0; k16 < 4; k16++) {
            const int kB = k16 * 32 + kh2;
            unsigned Ah[2][4];
#pragma unroll
            for (int mt = 0; mt < 2; mt++) {
                unsigned ar = abase + (wm * 32 + mt * 16 + lrow) * G2_PITCH + kB;
                ldm_x4(Ah[mt][0], Ah[mt][1], Ah[mt][2], Ah[mt][3], ar);
            }
#pragma unroll
            for (int bt = 0; bt < 4; bt++) {
                unsigned br = bbase + (wn * 64 + bt * 16 + lrow) * G2_PITCH + kB;
                unsigned b0, b1, b2, b3;
                ldm_x4(b0, b1, b2, b3, br);
#pragma unroll
                for (int mt = 0; mt < 2; mt++) {
                    mma16816f16(d[mt][bt][0], Ah[mt], b0, b2);
                    mma16816f16(d[mt][bt][1], Ah[mt], b1, b3);
                }
            }
        }
        __syncthreads();
    }

#pragma unroll
    for (int mt = 0; mt < 2; mt++) {
        int Rg0 = mty * 128 + wm * 32 + mt * 16 + (lane >> 2);
        int Rg1 = Rg0 + 8;
        float bi0 = __ldg(&d_bxr[Rg0]);
        float bi1 = __ldg(&d_bxr[Rg1]);
#pragma unroll
        for (int bt = 0; bt < 4; bt++)
#pragma unroll
            for (int hf = 0; hf < 2; hf++) {
                int col = wn * 64 + bt * 16 + hf * 8 + 2 * (lane & 3);
                int m = ntx * 128 + col;
                int s = m >> 6, b = m & 63;
                float* q = d[mt][bt][hf];
                *(float2*)(&d_gx[((size_t)s * NG + Rg0) * BB + b]) =
                    make_float2(q[0] + bi0, q[1] + bi0);
                *(float2*)(&d_gx[((size_t)s * NG + Rg1) * BB + b]) =
                    make_float2(q[2] + bi1, q[3] + bi1);
            }
    }
}

// =====================================================================
// persistent mma.sync step kernel — W hi-only (1-term), full barrier.
// 256 threads (8 warps, warp tile 16m x 16n), h fp16 ping-pong global,
// W (32 rows x 1024 fp16) in SMEM once. 4 chunks of k=256; per chunk:
// cp_wait<0>; sync; stage(kb+1); compute(kb). Per k16: 2 ldm + 2 mma.
// =====================================================================
#define W_PITCH 2064
#define WBYTES  (32 * W_PITCH)         // 66048
#define H_PITCH 528
#define HBUF (64 * H_PITCH)            // 33792
#define OFF_H   66048
#define OFF_SG  133632                 // 66048 + 2*33792
#define OFF_SGX 142336
#define TC_SMEM 151040

__global__ void __launch_bounds__(256, 1) persist_mma_kernel()
{
    extern __shared__ char smc[];
    float* sg  = (float*)(smc + OFF_SG);
    float* sgx = (float*)(smc + OFF_SGX);

    const int t = threadIdx.x, w = t >> 5, lane = t & 31;
    const int cta = blockIdx.x;
    const int wm = w >> 2, wn = w & 3;
    const unsigned smb = smem_u32(smc);

    // ---- stage W slab once: 32 rows x 2048 B ----
    const char* wsrc = (const char*)(d_whf + (size_t)cta * 32 * HID);
#pragma unroll
    for (int i = 0; i < 16; i++) {
        int u = t + i * 256;
        int r = u >> 7, q = u & 127;
        cp16(smc + r * W_PITCH + q * 16, wsrc + r * 2048 + q * 16);
    }
    cp_commit();

    const int lrow = lane & 15;
    const int kh2 = (lane >> 4) * 16;

    const int be = t & 63, jp = t >> 6;
    float creg[2] = {0.0f, 0.0f};

    // prefetch gx for s = 0
#pragma unroll
    for (int i = 0; i < 2; i++) {
        int u = t + i * 256;
        int r = u >> 4, bq = (u & 15) * 4;
        cp16((char*)sgx + (r * 68 + bq) * 4,
             d_gx + ((size_t)0 * NG + cta * 32 + r) * BB + bq);
    }
    cp_commit();
    cp_wait<0>();
    __syncthreads();

    for (int s = 0; s < SEQ; s++) {
        const char* hsrc = (const char*)d_hf16[s & 1];
        __half* hdst = d_hf16[(s + 1) & 1];

        auto stage_h = [&](int kb) {
            char* dst = smc + OFF_H + (kb & 1) * HBUF;
#pragma unroll
            for (int i = 0; i < 8; i++) {
                int u = t + i * 256;
                int r = u >> 5, q = u & 31;
                cp16(dst + r * H_PITCH + q * 16, hsrc + r * 2048 + kb * 512 + q * 16);
            }
            cp_commit();
        };

        stage_h(0);

        float d[2][4];
#pragma unroll
        for (int nt = 0; nt < 2; nt++)
#pragma unroll
            for (int q = 0; q < 4; q++) d[nt][q] = 0.0f;

        for (int kb = 0; kb < 4; kb++) {
            cp_wait<0>();          // chunk kb complete
            __syncthreads();       // all warps done with buf (kb+1)&1
            if (kb < 3) stage_h(kb + 1);

            const unsigned aw = smb + (wm * 16 + lrow) * W_PITCH + kb * 512;
            const unsigned hb = smb + OFF_H + (kb & 1) * HBUF + (wn * 16 + lrow) * H_PITCH;
#pragma unroll
            for (int k16 = 0; k16 < 16; k16++) {
                const int kB = k16 * 32 + kh2;
                unsigned ah[4];
                unsigned b0, b1, b2, b3;
                ldm_x4(ah[0], ah[1], ah[2], ah[3], aw + kB);
                ldm_x4(b0, b1, b2, b3, hb + kB);
                mma16816f16(d[0], ah, b0, b2);
                mma16816f16(d[1], ah, b1, b3);
            }
        }
        __syncthreads();           // all compute done before sg overwrite

#pragma unroll
        for (int nt = 0; nt < 2; nt++) {
            int col = wn * 16 + nt * 8 + (lane & 3) * 2;
            int row = wm * 16 + (lane >> 2);
            sg[row * 68 + col]           = d[nt][0];
            sg[row * 68 + col + 1]       = d[nt][1];
            sg[(row + 8) * 68 + col]     = d[nt][2];
            sg[(row + 8) * 68 + col + 1] = d[nt][3];
        }
        __syncthreads();

        unsigned short hph[2];
        float hf[2];
#pragma unroll
        for (int i = 0; i < 2; i++) {
            int jj = 2 * jp + i;
            float g[4];
#pragma unroll
            for (int gg = 0; gg < 4; gg++) {
                int r = gg * 8 + jj;
                g[gg] = sg[r * 68 + be] + sgx[r * 68 + be];
            }
            float it_ = sigf(g[0]);
            float ft  = sigf(g[1]);
            float gt  = tanhf(g[2]);
            float ot  = sigf(g[3]);
            float c = ft * creg[i] + it_ * gt;
            creg[i] = c;
            float h = ot * tanhf(c);
            hf[i] = h;
            __half hh = __float2half_rn(h);
            hph[i] = *(unsigned short*)&hh;
        }
        const int jglob = cta * 8 + 2 * jp;
        *(unsigned*)(&hdst[be * HID + jglob]) = *(unsigned*)hph;
        if (s == SEQ - 1)
            *(float2*)(&d_hfin[be * HID + jglob]) = make_float2(hf[0], hf[1]);

        // ---- barrier: arrive, prefetch gx(s+1) in the window, poll ----
        __threadfence();
        __syncthreads();
        if (t == 0) atomicAdd(&d_bar, 1);
        if (s + 1 < SEQ) {
#pragma unroll
            for (int i = 0; i < 2; i++) {
                int u = t + i * 256;
                int r = u >> 4, bq = (u & 15) * 4;
                cp16((char*)sgx + (r * 68 + bq) * 4,
                     d_gx + ((size_t)(s + 1) * NG + cta * 32 + r) * BB + bq);
            }
            cp_commit();
        }
        if (t == 0) {
            const int target = 128 * (s + 1);
            while (*(volatile int*)&d_bar < target) { }
        }
        __syncthreads();
    }

    const int jglob = cta * 8 + 2 * jp;
    *(float2*)(&d_cst[be * HID + jglob]) = make_float2(creg[0], creg[1]);
}

// =====================================================================
// head
// =====================================================================
__global__ void head_kernel(const float* __restrict__ Vw, const float* __restrict__ Vb,
                            float* __restrict__ out)
{
    const int b = blockIdx.x, t = threadIdx.x;
    float s0 = 0.0f, s1 = 0.0f;
    for (int k = t; k < HID; k += 256) {
        float hv = d_hfin[b * HID + k];
        s0 += hv * Vw[k];
        s1 += hv * Vw[HID + k];
        out[128 + b * HID + k] = hv;
        out[128 + BB * HID + b * HID + k] = d_cst[b * HID + k];
    }
    __shared__ float r0[256], r1[256];
    r0[t] = s0; r1[t] = s1;
    __syncthreads();
    for (int off = 128; off > 0; off >>= 1) {
        if (t < off) { r0[t] += r0[t + off]; r1[t] += r1[t + off]; }
        __syncthreads();
    }
    if (t == 0) {
        out[b * 2 + 0] = r0[0] + Vb[0];
        out[b * 2 + 1] = r1[0] + Vb[1];
    }
}

// =====================================================================
extern "C" void kernel_launch(void* const* d_in, const int* in_sizes, int n_in,
                              void* d_out, int out_size)
{
    (void)in_sizes; (void)n_in; (void)out_size;
    const int*   x   = (const int*)d_in[0];
    const float* emb = (const float*)d_in[1];

    cudaFuncSetAttribute(gx2_kernel,         cudaFuncAttributeMaxDynamicSharedMemorySize, G2_SMEM);
    cudaFuncSetAttribute(persist_mma_kernel, cudaFuncAttributeMaxDynamicSharedMemorySize, TC_SMEM);

    prepack_kernel<<<1024, 256>>>(
        (const float*)d_in[2],  (const float*)d_in[3],  (const float*)d_in[4],
        (const float*)d_in[5],  (const float*)d_in[6],  (const float*)d_in[7],
        (const float*)d_in[8],  (const float*)d_in[9],  (const float*)d_in[10],
        (const float*)d_in[11], (const float*)d_in[12], (const float*)d_in[13]);

    gather_kernel<<<2048, 256>>>(x, emb);

    gx2_kernel<<<dim3(32, 256), 256, G2_SMEM>>>();

    persist_mma_kernel<<<128, 256, TC_SMEM>>>();

    head_kernel<<<BB, 256>>>((const float*)d_in[14], (const float*)d_in[15], (float*)d_out);
}